// round 5
// baseline (speedup 1.0000x reference)
#include <cuda_runtime.h>
#include <cstdint>

#define NAG   8
#define BATCH 32768
#define SDIM  128
#define ADIM  16
#define HID   128
#define HEADS 4
#define AD    32

// ---------------- scratch (device globals; no allocation allowed) ----------------
__device__ float g_sa   [(size_t)NAG * BATCH * HID];
__device__ float g_se   [(size_t)NAG * BATCH * HID];
__device__ float g_Kb   [(size_t)NAG * BATCH * HID];
__device__ float g_Qb   [(size_t)NAG * BATCH * HID];
__device__ float g_Vb   [(size_t)NAG * BATCH * HID];
__device__ float g_oth  [(size_t)NAG * BATCH * HID];
__device__ float g_h1   [(size_t)NAG * BATCH * HID];

__device__ __forceinline__ unsigned totf32(float x) {
    unsigned u;
    asm("cvt.rna.tf32.f32 %0, %1;" : "=r"(u) : "f"(x));
    return u;
}

// ---------------- dual-output tensor-core GEMM (tf32, fp32 accumulate) ------------
// Computes, per agent n, a BM x BN tile of [C0 | C1] = act([A1|A2] @ [W0|W1] + b).
// Each 128-wide output half has its own W (std per-agent [km][128] or headpacked
// [HEADS][HID][AD]), bias, relu flag, valid-k count km, and 128-wide output buffer.
// 8 warps, each a 64x64 tile of 4x8 m16n8k8 mma ops. KT=8, double-buffered smem.
// Banking: strides ≡ 8 (mod 32) make fragment loads a perfect 32-bank bijection.
template<int BM, int BN>
__global__ void __launch_bounds__(256)
gemm_tc(const float* __restrict__ A1, int a1w,
        const float* __restrict__ A2, int a2w, int Ktot,
        const float* __restrict__ W0, int hp0, const float* __restrict__ b0v,
        int relu0, float* __restrict__ C0, int km0,
        const float* __restrict__ W1, int hp1, const float* __restrict__ b1v,
        int relu1, float* __restrict__ C1, int km1)
{
    constexpr int KT = 8;
    constexpr int STRA = BM + 8;    // ≡ 8 mod 32
    constexpr int STRB = BN + 8;
    __shared__ unsigned As[2][KT * STRA];
    __shared__ unsigned Bs[2][KT * STRB];

    int n   = blockIdx.z;
    int b0g = blockIdx.x * BM;
    const float* A1n = A1 + (size_t)n * BATCH * a1w;
    const float* A2n = A2 ? (A2 + (size_t)n * BATCH * a2w) : A1;
    const float* W0n = hp0 ? W0 : (W0 + (size_t)n * km0 * 128);
    const float* W1n = W1 ? (hp1 ? W1 : (W1 + (size_t)n * km1 * 128)) : nullptr;
    const float* b0n = b0v ? (hp0 ? b0v : b0v + n * 128) : nullptr;
    const float* b1n = b1v ? (hp1 ? b1v : b1v + n * 128) : nullptr;
    float* C0n = C0 + (size_t)n * BATCH * 128;
    float* C1n = C1 ? (C1 + (size_t)n * BATCH * 128) : nullptr;

    int tid  = threadIdx.x;
    int wid  = tid >> 5, lane = tid & 31;
    int grp  = lane >> 2, tig = lane & 3;
    constexpr int WNW = BN / 64;            // warps along N
    int wm = (wid / WNW) * 64;
    int wn = (wid % WNW) * 64;

    // staging mappings
    int arow = (BM == 256) ? tid : (tid >> 1);
    int aak  = (BM == 256) ? 0 : ((tid & 1) << 2);
    int krow = tid >> 5;                                  // 0..7
    int bcol = (BN == 256) ? ((tid & 31) << 3) : ((tid & 31) << 2);

    auto aix = [](int k, int m) { return k * STRA + (((k >> 2) & 1) << 2) + m; };

    float acc[4][8][4];
    #pragma unroll
    for (int mt = 0; mt < 4; mt++)
        #pragma unroll
        for (int nt = 0; nt < 8; nt++)
            #pragma unroll
            for (int r = 0; r < 4; r++) acc[mt][nt][r] = 0.f;

    int nkt = Ktot >> 3;
    float4 va0, va1, wv0, wv1;

    auto ldtile = [&](int kt) {
        int k0 = kt * KT;
        const float* src; int srcw, kbase;
        if (k0 < a1w) { src = A1n; srcw = a1w; kbase = k0; }
        else          { src = A2n; srcw = a2w; kbase = k0 - a1w; }
        va0 = *(const float4*)(src + (size_t)(b0g + arow) * srcw + kbase + aak);
        if (BM == 256)
            va1 = *(const float4*)(src + (size_t)(b0g + arow) * srcw + kbase + 4);
        int k  = k0 + krow;
        int h  = (BN == 256) ? (bcol >> 7) : 0;
        int lc = bcol & 127;
        const float* Wh = h ? W1n : W0n;
        int hph = h ? hp1 : hp0;
        int kmh = h ? km1 : km0;
        if (k < kmh) {
            const float* wp = hph
                ? Wh + (size_t)(lc >> 5) * (HID * AD) + (size_t)k * AD + (lc & 31)
                : Wh + (size_t)k * 128 + lc;
            wv0 = *(const float4*)wp;
            if (BN == 256) wv1 = *(const float4*)(wp + 4);
        } else {
            wv0 = make_float4(0.f, 0.f, 0.f, 0.f);
            if (BN == 256) wv1 = wv0;
        }
    };
    auto ststile = [&](int buf) {
        unsigned* Ab = As[buf];
        if (BM == 256) {
            Ab[aix(0, arow)] = totf32(va0.x);
            Ab[aix(1, arow)] = totf32(va0.y);
            Ab[aix(2, arow)] = totf32(va0.z);
            Ab[aix(3, arow)] = totf32(va0.w);
            Ab[aix(4, arow)] = totf32(va1.x);
            Ab[aix(5, arow)] = totf32(va1.y);
            Ab[aix(6, arow)] = totf32(va1.z);
            Ab[aix(7, arow)] = totf32(va1.w);
        } else {
            Ab[aix(aak + 0, arow)] = totf32(va0.x);
            Ab[aix(aak + 1, arow)] = totf32(va0.y);
            Ab[aix(aak + 2, arow)] = totf32(va0.z);
            Ab[aix(aak + 3, arow)] = totf32(va0.w);
        }
        unsigned* Bb = Bs[buf];
        uint4 u0 = { totf32(wv0.x), totf32(wv0.y), totf32(wv0.z), totf32(wv0.w) };
        *(uint4*)&Bb[krow * STRB + bcol] = u0;
        if (BN == 256) {
            uint4 u1 = { totf32(wv1.x), totf32(wv1.y), totf32(wv1.z), totf32(wv1.w) };
            *(uint4*)&Bb[krow * STRB + bcol + 4] = u1;
        }
    };

    ldtile(0);
    ststile(0);
    __syncthreads();

    for (int kt = 0; kt < nkt; kt++) {
        int buf = kt & 1;
        if (kt + 1 < nkt) ldtile(kt + 1);

        const unsigned* Ab = As[buf];
        const unsigned* Bb = Bs[buf];
        unsigned af[4][4];
        #pragma unroll
        for (int mt = 0; mt < 4; mt++) {
            int m = wm + mt * 16 + grp;
            af[mt][0] = Ab[aix(tig, m)];
            af[mt][1] = Ab[aix(tig, m + 8)];
            af[mt][2] = Ab[aix(tig + 4, m)];
            af[mt][3] = Ab[aix(tig + 4, m + 8)];
        }
        unsigned bf[8][2];
        #pragma unroll
        for (int nt = 0; nt < 8; nt++) {
            int c = wn + nt * 8 + grp;
            bf[nt][0] = Bb[tig * STRB + c];
            bf[nt][1] = Bb[(tig + 4) * STRB + c];
        }
        #pragma unroll
        for (int mt = 0; mt < 4; mt++)
            #pragma unroll
            for (int nt = 0; nt < 8; nt++)
                asm("mma.sync.aligned.m16n8k8.row.col.f32.tf32.tf32.f32 "
                    "{%0,%1,%2,%3}, {%4,%5,%6,%7}, {%8,%9}, {%0,%1,%2,%3};"
                    : "+f"(acc[mt][nt][0]), "+f"(acc[mt][nt][1]),
                      "+f"(acc[mt][nt][2]), "+f"(acc[mt][nt][3])
                    : "r"(af[mt][0]), "r"(af[mt][1]), "r"(af[mt][2]), "r"(af[mt][3]),
                      "r"(bf[nt][0]), "r"(bf[nt][1]));
        if (kt + 1 < nkt) ststile(buf ^ 1);
        __syncthreads();
    }

    // ---- epilogue: per-half bias + relu + store ----
    #pragma unroll
    for (int nt = 0; nt < 8; nt++) {
        int gc = wn + nt * 8 + tig * 2;
        int h  = (BN == 256) ? (gc >> 7) : 0;
        int lc = gc & 127;
        const float* bh = h ? b1n : b0n;
        int rh = h ? relu1 : relu0;
        float* Ch = h ? C1n : C0n;
        float bj0 = bh ? bh[lc]     : 0.f;
        float bj1 = bh ? bh[lc + 1] : 0.f;
        #pragma unroll
        for (int mt = 0; mt < 4; mt++) {
            int row0 = b0g + wm + mt * 16 + grp;
            float v0 = acc[mt][nt][0] + bj0;
            float v1 = acc[mt][nt][1] + bj1;
            float v2 = acc[mt][nt][2] + bj0;
            float v3 = acc[mt][nt][3] + bj1;
            if (rh) {
                v0 = fmaxf(v0, 0.f); v1 = fmaxf(v1, 0.f);
                v2 = fmaxf(v2, 0.f); v3 = fmaxf(v3, 0.f);
            }
            *(float2*)&Ch[(size_t)row0 * 128 + lc]       = make_float2(v0, v1);
            *(float2*)&Ch[(size_t)(row0 + 8) * 128 + lc] = make_float2(v2, v3);
        }
    }
}

// ---------------- attention (exact fp32) ------------------------------------------
__global__ void attn_kernel()
{
    __shared__ float Ks[4 * 8 * 128];
    __shared__ float Vs[4 * 8 * 128];
    int tid = threadIdx.x;
    int b0  = blockIdx.x * 4;

    #pragma unroll
    for (int t = 0; t < 8; t++) {
        int f  = tid + t * 128;
        int c4 = f & 31;
        int r  = (f >> 5) & 3;
        int j  = f >> 7;
        size_t g = ((size_t)j * BATCH + b0 + r) * 128 + c4 * 4;
        int s = (r * 8 + j) * 128 + c4 * 4;
        *(float4*)&Ks[s] = *(const float4*)&g_Kb[g];
        *(float4*)&Vs[s] = *(const float4*)&g_Vb[g];
    }
    __syncthreads();

    int r = tid >> 5, k = (tid >> 3) & 3, i = tid & 7;
    float q[32];
    size_t base = ((size_t)i * BATCH + b0 + r) * 128 + k * 32;
    #pragma unroll
    for (int t = 0; t < 8; t++)
        *(float4*)&q[t * 4] = *(const float4*)&g_Qb[base + t * 4];

    float lg[8];
    #pragma unroll
    for (int j = 0; j < 8; j++) {
        const float* kp = &Ks[(r * 8 + j) * 128 + k * 32];
        float d = 0.f;
        #pragma unroll
        for (int dd = 0; dd < 32; dd++) d += q[dd] * kp[dd];
        lg[j] = (j == i) ? -1e9f : d * 0.17677669529663687f;
    }
    float m = lg[0];
    #pragma unroll
    for (int j = 1; j < 8; j++) m = fmaxf(m, lg[j]);
    float ssum = 0.f;
    #pragma unroll
    for (int j = 0; j < 8; j++) { lg[j] = __expf(lg[j] - m); ssum += lg[j]; }
    float inv = 1.f / ssum;

    float acc[32];
    #pragma unroll
    for (int dd = 0; dd < 32; dd++) acc[dd] = 0.f;
    #pragma unroll
    for (int j = 0; j < 8; j++) {
        float p = lg[j] * inv;
        const float* vp = &Vs[(r * 8 + j) * 128 + k * 32];
        #pragma unroll
        for (int dd = 0; dd < 32; dd++) acc[dd] += p * vp[dd];
    }
    #pragma unroll
    for (int t = 0; t < 8; t++)
        *(float4*)&g_oth[base + t * 4] = *(float4*)&acc[t * 4];
}

// ---------------- all_q + argmax gather (exact fp32) ------------------------------
__global__ void allq_kernel(const float* __restrict__ actions,
                            const float* __restrict__ Wc2,
                            const float* __restrict__ bc2,
                            float* __restrict__ out)
{
    __shared__ float Wc2s[128 * 16];
    __shared__ float bc2s[16];
    int n = blockIdx.z;
    int b0 = blockIdx.x * 256;
    int tid = threadIdx.x;
    const float* Wc2n = Wc2 + (size_t)n * 128 * 16;

    #pragma unroll
    for (int t = 0; t < 2; t++) {
        int f = tid + t * 256;
        *(float4*)&Wc2s[f * 4] = *(const float4*)&Wc2n[f * 4];
    }
    if (tid < 16) bc2s[tid] = bc2[n * 16 + tid];
    __syncthreads();

    int b = b0 + tid;
    const float* ap = actions + ((size_t)n * BATCH + b) * 16;
    float best = ap[0]; int a = 0;
    #pragma unroll
    for (int c = 1; c < 16; c++) { float v = ap[c]; if (v > best) { best = v; a = c; } }

    const float* hp = g_h1 + ((size_t)n * BATCH + b) * 128;
    float acc = 0.f;
    #pragma unroll
    for (int h4 = 0; h4 < 128; h4 += 4) {
        float4 hv = *(const float4*)&hp[h4];
        acc += hv.x * Wc2s[(h4 + 0) * 16 + a];
        acc += hv.y * Wc2s[(h4 + 1) * 16 + a];
        acc += hv.z * Wc2s[(h4 + 2) * 16 + a];
        acc += hv.w * Wc2s[(h4 + 3) * 16 + a];
    }
    out[(size_t)n * BATCH + b] = acc + bc2s[a];
}

// ---------------- launch -----------------------------------------------------------
extern "C" void kernel_launch(void* const* d_in, const int* in_sizes, int n_in,
                              void* d_out, int out_size)
{
    const float* states  = (const float*)d_in[0];
    const float* actions = (const float*)d_in[1];
    const float* We      = (const float*)d_in[2];
    const float* be      = (const float*)d_in[3];
    const float* Wse     = (const float*)d_in[4];
    const float* bs      = (const float*)d_in[5];
    const float* Wk      = (const float*)d_in[6];
    const float* Wq      = (const float*)d_in[7];
    const float* Wv      = (const float*)d_in[8];
    const float* bv      = (const float*)d_in[9];
    const float* Wc1     = (const float*)d_in[10];
    const float* bc1     = (const float*)d_in[11];
    const float* Wc2     = (const float*)d_in[12];
    const float* bc2     = (const float*)d_in[13];
    float* out = (float*)d_out;

    float *p_sa, *p_se, *p_K, *p_Q, *p_V, *p_oth, *p_h1;
    cudaGetSymbolAddress((void**)&p_sa,  g_sa);
    cudaGetSymbolAddress((void**)&p_se,  g_se);
    cudaGetSymbolAddress((void**)&p_K,   g_Kb);
    cudaGetSymbolAddress((void**)&p_Q,   g_Qb);
    cudaGetSymbolAddress((void**)&p_V,   g_Vb);
    cudaGetSymbolAddress((void**)&p_oth, g_oth);
    cudaGetSymbolAddress((void**)&p_h1,  g_h1);

    dim3 gridN(BATCH / 128, 1, NAG);   // BM=128 kernels
    dim3 gridM(BATCH / 256, 1, NAG);   // BM=256 kernels

    // fused encoders: [sa_enc | s_enc], K=144 (Ws zero-padded past k=128)
    gemm_tc<128, 256><<<gridN, 256>>>(states, SDIM, actions, ADIM, SDIM + ADIM,
                                      We, 0, be, 1, p_sa, 144,
                                      Wse, 0, bs, 1, p_se, 128);
    // fused K|V from sa_enc
    gemm_tc<128, 256><<<gridN, 256>>>(p_sa, HID, nullptr, 0, HID,
                                      Wk, 1, nullptr, 0, p_K, 128,
                                      Wv, 1, bv, 1, p_V, 128);
    // Q from s_enc
    gemm_tc<256, 128><<<gridM, 256>>>(p_se, HID, nullptr, 0, HID,
                                      Wq, 1, nullptr, 0, p_Q, 128,
                                      nullptr, 0, nullptr, 0, nullptr, 0);
    // attention
    attn_kernel<<<BATCH / 4, 128>>>();
    // critic hidden: h1 = relu([s_enc | other] @ Wc1 + bc1), K=256
    gemm_tc<256, 128><<<gridM, 256>>>(p_se, HID, p_oth, HID, 2 * HID,
                                      Wc1, 0, bc1, 1, p_h1, 256,
                                      nullptr, 0, nullptr, 0, nullptr, 0);
    // all_q + gather
    allq_kernel<<<dim3(BATCH / 256, 1, NAG), 256>>>(actions, Wc2, bc2, out);
}

// round 6
// speedup vs baseline: 1.4217x; 1.4217x over previous
#include <cuda_runtime.h>
#include <cstdint>

#define NAG   8
#define BATCH 32768
#define SDIM  128
#define ADIM  16
#define HID   128
#define HEADS 4
#define AD    32

// ---------------- scratch (device globals; no allocation allowed) ----------------
__device__ float g_sa   [(size_t)NAG * BATCH * HID];
__device__ float g_se   [(size_t)NAG * BATCH * HID];
__device__ float g_Kb   [(size_t)NAG * BATCH * HID];
__device__ float g_Qb   [(size_t)NAG * BATCH * HID];
__device__ float g_Vb   [(size_t)NAG * BATCH * HID];
__device__ float g_oth  [(size_t)NAG * BATCH * HID];

__device__ __forceinline__ unsigned totf32(float x) {
    unsigned u;
    asm("cvt.rna.tf32.f32 %0, %1;" : "=r"(u) : "f"(x));
    return u;
}

// A smem addressing: word = k*136 + 4*((k>>2)&1) + m  (conflict-free frag loads).
__device__ __forceinline__ int AIDX(int k, int m) {
    return k * 136 + (((k >> 2) & 1) << 2) + m;
}
__device__ __forceinline__ int BIDX(int k, int n) {
    return k * 136 + n;
}

// ---------------- per-agent GEMM on tensor cores (tf32, fp32 accumulate) ----------
// (Round-4 proven config: 128x128 block, 8 warps 2x4, warp 64x32, KT=16.)
__global__ void __launch_bounds__(256)
gemm128_tc(const float* __restrict__ A1, int a1w,
           const float* __restrict__ A2, int a2w,
           const float* __restrict__ W, int headpacked,
           const float* __restrict__ bias, int dorelu,
           float* __restrict__ C, int Ktot)
{
    const int KT = 16, TSZ = 16 * 136;
    __shared__ unsigned As[2][TSZ];
    __shared__ unsigned Bs[2][TSZ];

    int n   = blockIdx.z;
    int b0g = blockIdx.x * 128;
    const float* A1n = A1 + (size_t)n * BATCH * a1w;
    const float* A2n = A2 ? (A2 + (size_t)n * BATCH * a2w) : A1;
    const float* Wn  = headpacked ? W : (W + (size_t)n * Ktot * 128);
    const float* bn  = bias ? (headpacked ? bias : bias + n * 128) : nullptr;
    float* Cn = C + (size_t)n * BATCH * 128;

    int tid  = threadIdx.x;
    int wid  = tid >> 5, lane = tid & 31;
    int grp  = lane >> 2, tig = lane & 3;
    int wm   = (wid >> 2) * 64;
    int wn   = (wid & 3) * 32;

    int arow = tid >> 2;
    int ak   = (tid & 3) << 2;
    int krow = tid >> 4;
    int wcol = (tid & 15) << 3;

    float acc[4][4][4];
    #pragma unroll
    for (int mt = 0; mt < 4; mt++)
        #pragma unroll
        for (int nt = 0; nt < 4; nt++)
            #pragma unroll
            for (int r = 0; r < 4; r++) acc[mt][nt][r] = 0.f;

    int nkt = Ktot >> 4;
    float4 va0, va1, vw0, vw1;

    auto ldtile = [&](int kt) {
        int k0 = kt * KT;
        const float* src; int srcw, kbase;
        if (k0 < a1w) { src = A1n; srcw = a1w; kbase = k0; }
        else          { src = A2n; srcw = a2w; kbase = k0 - a1w; }
        va0 = *(const float4*)(src + (size_t)(b0g + arow)      * srcw + kbase + ak);
        va1 = *(const float4*)(src + (size_t)(b0g + arow + 64) * srcw + kbase + ak);
        const float* wp;
        if (!headpacked) wp = Wn + (size_t)(k0 + krow) * 128 + wcol;
        else             wp = Wn + (size_t)(wcol >> 5) * (HID * AD) + (size_t)(k0 + krow) * AD + (wcol & 31);
        vw0 = *(const float4*)wp;
        vw1 = *(const float4*)(wp + 4);
    };
    auto ststile = [&](int buf) {
        unsigned* Ab = As[buf];
        Ab[AIDX(ak + 0, arow)]      = totf32(va0.x);
        Ab[AIDX(ak + 1, arow)]      = totf32(va0.y);
        Ab[AIDX(ak + 2, arow)]      = totf32(va0.z);
        Ab[AIDX(ak + 3, arow)]      = totf32(va0.w);
        Ab[AIDX(ak + 0, arow + 64)] = totf32(va1.x);
        Ab[AIDX(ak + 1, arow + 64)] = totf32(va1.y);
        Ab[AIDX(ak + 2, arow + 64)] = totf32(va1.z);
        Ab[AIDX(ak + 3, arow + 64)] = totf32(va1.w);
        unsigned* Bb = Bs[buf];
        uint4 w0 = { totf32(vw0.x), totf32(vw0.y), totf32(vw0.z), totf32(vw0.w) };
        uint4 w1 = { totf32(vw1.x), totf32(vw1.y), totf32(vw1.z), totf32(vw1.w) };
        *(uint4*)&Bb[BIDX(krow, wcol)]     = w0;
        *(uint4*)&Bb[BIDX(krow, wcol + 4)] = w1;
    };

    ldtile(0);
    ststile(0);
    __syncthreads();

    for (int kt = 0; kt < nkt; kt++) {
        int buf = kt & 1;
        if (kt + 1 < nkt) ldtile(kt + 1);
        const unsigned* Ab = As[buf];
        const unsigned* Bb = Bs[buf];
        #pragma unroll
        for (int ks = 0; ks < 2; ks++) {
            int k0r = ks * 8 + tig;
            int k4r = ks * 8 + tig + 4;
            unsigned af[4][4];
            #pragma unroll
            for (int mt = 0; mt < 4; mt++) {
                int m = wm + mt * 16 + grp;
                af[mt][0] = Ab[AIDX(k0r, m)];
                af[mt][1] = Ab[AIDX(k0r, m + 8)];
                af[mt][2] = Ab[AIDX(k4r, m)];
                af[mt][3] = Ab[AIDX(k4r, m + 8)];
            }
            unsigned bf[4][2];
            #pragma unroll
            for (int nt = 0; nt < 4; nt++) {
                int c = wn + nt * 8 + grp;
                bf[nt][0] = Bb[BIDX(k0r, c)];
                bf[nt][1] = Bb[BIDX(k4r, c)];
            }
            #pragma unroll
            for (int mt = 0; mt < 4; mt++)
                #pragma unroll
                for (int nt = 0; nt < 4; nt++)
                    asm("mma.sync.aligned.m16n8k8.row.col.f32.tf32.tf32.f32 "
                        "{%0,%1,%2,%3}, {%4,%5,%6,%7}, {%8,%9}, {%0,%1,%2,%3};"
                        : "+f"(acc[mt][nt][0]), "+f"(acc[mt][nt][1]),
                          "+f"(acc[mt][nt][2]), "+f"(acc[mt][nt][3])
                        : "r"(af[mt][0]), "r"(af[mt][1]), "r"(af[mt][2]), "r"(af[mt][3]),
                          "r"(bf[nt][0]), "r"(bf[nt][1]));
        }
        if (kt + 1 < nkt) ststile(buf ^ 1);
        __syncthreads();
    }

    #pragma unroll
    for (int nt = 0; nt < 4; nt++) {
        int col = wn + nt * 8 + tig * 2;
        float bj0 = bn ? bn[col]     : 0.f;
        float bj1 = bn ? bn[col + 1] : 0.f;
        #pragma unroll
        for (int mt = 0; mt < 4; mt++) {
            int row0 = b0g + wm + mt * 16 + grp;
            float v0 = acc[mt][nt][0] + bj0;
            float v1 = acc[mt][nt][1] + bj1;
            float v2 = acc[mt][nt][2] + bj0;
            float v3 = acc[mt][nt][3] + bj1;
            if (dorelu) {
                v0 = fmaxf(v0, 0.f); v1 = fmaxf(v1, 0.f);
                v2 = fmaxf(v2, 0.f); v3 = fmaxf(v3, 0.f);
            }
            *(float2*)&Cn[(size_t)row0 * 128 + col]       = make_float2(v0, v1);
            *(float2*)&Cn[(size_t)(row0 + 8) * 128 + col] = make_float2(v2, v3);
        }
    }
}

// ---------------- fused critic: h1 GEMM (K=256) + all_q + argmax gather -----------
// Same mainloop as gemm128_tc (A=[s_enc|other], W=Wc1). Epilogue never writes h1:
// out[row] = sum_col relu(h1) * Wc2[col, argmax(actions[row])] + bc2[argmax].
__global__ void __launch_bounds__(256)
critic_tc(const float* __restrict__ actions,
          const float* __restrict__ Wc1, const float* __restrict__ bc1,
          const float* __restrict__ Wc2, const float* __restrict__ bc2,
          float* __restrict__ out)
{
    const int KT = 16, TSZ = 16 * 136;
    __shared__ unsigned As[2][TSZ];
    __shared__ unsigned Bs[2][TSZ];
    __shared__ float Wc2s[128 * 16];
    __shared__ float bc1s[128];
    __shared__ float bc2s[16];
    __shared__ float rowacc[128];
    __shared__ int   amaxs[128];

    int n   = blockIdx.z;
    int b0g = blockIdx.x * 128;
    const float* A1n = g_se  + (size_t)n * BATCH * 128;
    const float* A2n = g_oth + (size_t)n * BATCH * 128;
    const float* Wn  = Wc1 + (size_t)n * 256 * 128;
    const float* Wc2n = Wc2 + (size_t)n * 128 * 16;

    int tid  = threadIdx.x;
    int wid  = tid >> 5, lane = tid & 31;
    int grp  = lane >> 2, tig = lane & 3;
    int wm   = (wid >> 2) * 64;
    int wn   = (wid & 3) * 32;
    int arow = tid >> 2;
    int ak   = (tid & 3) << 2;
    int krow = tid >> 4;
    int wcol = (tid & 15) << 3;

    // stage epilogue data (ordered before first __syncthreads)
    #pragma unroll
    for (int t = 0; t < 2; t++) {
        int f = tid + t * 256;
        *(float4*)&Wc2s[f * 4] = *(const float4*)&Wc2n[f * 4];
    }
    if (tid < 128) {
        bc1s[tid] = bc1[n * 128 + tid];
        rowacc[tid] = 0.f;
        const float* ap = actions + ((size_t)n * BATCH + b0g + tid) * 16;
        float best = ap[0]; int bi = 0;
        #pragma unroll
        for (int c = 1; c < 16; c++) { float v = ap[c]; if (v > best) { best = v; bi = c; } }
        amaxs[tid] = bi;
    }
    if (tid < 16) bc2s[tid] = bc2[n * 16 + tid];

    float acc[4][4][4];
    #pragma unroll
    for (int mt = 0; mt < 4; mt++)
        #pragma unroll
        for (int nt = 0; nt < 4; nt++)
            #pragma unroll
            for (int r = 0; r < 4; r++) acc[mt][nt][r] = 0.f;

    const int nkt = 16;   // K = 256
    float4 va0, va1, vw0, vw1;

    auto ldtile = [&](int kt) {
        int k0 = kt * KT;
        const float* src = (k0 < 128) ? A1n : A2n;
        int kbase = (k0 < 128) ? k0 : (k0 - 128);
        va0 = *(const float4*)(src + (size_t)(b0g + arow)      * 128 + kbase + ak);
        va1 = *(const float4*)(src + (size_t)(b0g + arow + 64) * 128 + kbase + ak);
        const float* wp = Wn + (size_t)(k0 + krow) * 128 + wcol;
        vw0 = *(const float4*)wp;
        vw1 = *(const float4*)(wp + 4);
    };
    auto ststile = [&](int buf) {
        unsigned* Ab = As[buf];
        Ab[AIDX(ak + 0, arow)]      = totf32(va0.x);
        Ab[AIDX(ak + 1, arow)]      = totf32(va0.y);
        Ab[AIDX(ak + 2, arow)]      = totf32(va0.z);
        Ab[AIDX(ak + 3, arow)]      = totf32(va0.w);
        Ab[AIDX(ak + 0, arow + 64)] = totf32(va1.x);
        Ab[AIDX(ak + 1, arow + 64)] = totf32(va1.y);
        Ab[AIDX(ak + 2, arow + 64)] = totf32(va1.z);
        Ab[AIDX(ak + 3, arow + 64)] = totf32(va1.w);
        unsigned* Bb = Bs[buf];
        uint4 w0 = { totf32(vw0.x), totf32(vw0.y), totf32(vw0.z), totf32(vw0.w) };
        uint4 w1 = { totf32(vw1.x), totf32(vw1.y), totf32(vw1.z), totf32(vw1.w) };
        *(uint4*)&Bb[BIDX(krow, wcol)]     = w0;
        *(uint4*)&Bb[BIDX(krow, wcol + 4)] = w1;
    };

    ldtile(0);
    ststile(0);
    __syncthreads();

    for (int kt = 0; kt < nkt; kt++) {
        int buf = kt & 1;
        if (kt + 1 < nkt) ldtile(kt + 1);
        const unsigned* Ab = As[buf];
        const unsigned* Bb = Bs[buf];
        #pragma unroll
        for (int ks = 0; ks < 2; ks++) {
            int k0r = ks * 8 + tig;
            int k4r = ks * 8 + tig + 4;
            unsigned af[4][4];
            #pragma unroll
            for (int mt = 0; mt < 4; mt++) {
                int m = wm + mt * 16 + grp;
                af[mt][0] = Ab[AIDX(k0r, m)];
                af[mt][1] = Ab[AIDX(k0r, m + 8)];
                af[mt][2] = Ab[AIDX(k4r, m)];
                af[mt][3] = Ab[AIDX(k4r, m + 8)];
            }
            unsigned bf[4][2];
            #pragma unroll
            for (int nt = 0; nt < 4; nt++) {
                int c = wn + nt * 8 + grp;
                bf[nt][0] = Bb[BIDX(k0r, c)];
                bf[nt][1] = Bb[BIDX(k4r, c)];
            }
            #pragma unroll
            for (int mt = 0; mt < 4; mt++)
                #pragma unroll
                for (int nt = 0; nt < 4; nt++)
                    asm("mma.sync.aligned.m16n8k8.row.col.f32.tf32.tf32.f32 "
                        "{%0,%1,%2,%3}, {%4,%5,%6,%7}, {%8,%9}, {%0,%1,%2,%3};"
                        : "+f"(acc[mt][nt][0]), "+f"(acc[mt][nt][1]),
                          "+f"(acc[mt][nt][2]), "+f"(acc[mt][nt][3])
                        : "r"(af[mt][0]), "r"(af[mt][1]), "r"(af[mt][2]), "r"(af[mt][3]),
                          "r"(bf[nt][0]), "r"(bf[nt][1]));
        }
        if (kt + 1 < nkt) ststile(buf ^ 1);
        __syncthreads();
    }

    // ---- fused epilogue: relu(h1)·Wc2[:,a] partial dots, quad-reduce, smem add ----
    #pragma unroll
    for (int mt = 0; mt < 4; mt++) {
        int row0 = wm + mt * 16 + grp;       // local rows row0, row0+8
        int a0 = amaxs[row0];
        int a1 = amaxs[row0 + 8];
        float p0 = 0.f, p1 = 0.f;
        #pragma unroll
        for (int nt = 0; nt < 4; nt++) {
            int col = wn + nt * 8 + tig * 2;
            float bj0 = bc1s[col], bj1 = bc1s[col + 1];
            float h00 = fmaxf(acc[mt][nt][0] + bj0, 0.f);
            float h01 = fmaxf(acc[mt][nt][1] + bj1, 0.f);
            float h10 = fmaxf(acc[mt][nt][2] + bj0, 0.f);
            float h11 = fmaxf(acc[mt][nt][3] + bj1, 0.f);
            p0 += h00 * Wc2s[col * 16 + a0] + h01 * Wc2s[(col + 1) * 16 + a0];
            p1 += h10 * Wc2s[col * 16 + a1] + h11 * Wc2s[(col + 1) * 16 + a1];
        }
        p0 += __shfl_xor_sync(0xffffffffu, p0, 1);
        p0 += __shfl_xor_sync(0xffffffffu, p0, 2);
        p1 += __shfl_xor_sync(0xffffffffu, p1, 1);
        p1 += __shfl_xor_sync(0xffffffffu, p1, 2);
        if (tig == 0) {
            atomicAdd(&rowacc[row0], p0);
            atomicAdd(&rowacc[row0 + 8], p1);
        }
    }
    __syncthreads();
    if (tid < 128)
        out[(size_t)n * BATCH + b0g + tid] = rowacc[tid] + bc2s[amaxs[tid]];
}

// ---------------- attention (exact fp32, half-headdim per thread) ------------------
// 256 threads, 4 batch rows/block. tid -> hf(bit0), i(1..3), k(4..5), r(6..7).
// Dot over full 32 dims combined via shfl_xor(1) with the hf-partner lane.
__global__ void __launch_bounds__(256)
attn_kernel()
{
    __shared__ float Ks[4 * 8 * 128];
    __shared__ float Vs[4 * 8 * 128];
    int tid = threadIdx.x;
    int b0  = blockIdx.x * 4;

    #pragma unroll
    for (int t = 0; t < 4; t++) {
        int f  = tid + t * 256;      // float4 index, 1024 per array
        int c4 = f & 31;
        int r  = (f >> 5) & 3;
        int j  = f >> 7;
        size_t g = ((size_t)j * BATCH + b0 + r) * 128 + c4 * 4;
        int s = (r * 8 + j) * 128 + c4 * 4;
        *(float4*)&Ks[s] = *(const float4*)&g_Kb[g];
        *(float4*)&Vs[s] = *(const float4*)&g_Vb[g];
    }
    __syncthreads();

    int hf = tid & 1;
    int i  = (tid >> 1) & 7;
    int k  = (tid >> 4) & 3;
    int r  = tid >> 6;

    float q[16];
    size_t base = ((size_t)i * BATCH + b0 + r) * 128 + k * 32 + hf * 16;
    #pragma unroll
    for (int t = 0; t < 4; t++)
        *(float4*)&q[t * 4] = *(const float4*)&g_Qb[base + t * 4];

    float lg[8];
    #pragma unroll
    for (int j = 0; j < 8; j++) {
        const float* kp = &Ks[(r * 8 + j) * 128 + k * 32 + hf * 16];
        float d = 0.f;
        #pragma unroll
        for (int dd = 0; dd < 16; dd++) d += q[dd] * kp[dd];
        d += __shfl_xor_sync(0xffffffffu, d, 1);   // combine hf halves
        lg[j] = (j == i) ? -1e9f : d * 0.17677669529663687f;
    }
    float m = lg[0];
    #pragma unroll
    for (int j = 1; j < 8; j++) m = fmaxf(m, lg[j]);
    float ssum = 0.f;
    #pragma unroll
    for (int j = 0; j < 8; j++) { lg[j] = __expf(lg[j] - m); ssum += lg[j]; }
    float inv = 1.f / ssum;

    float acc[16];
    #pragma unroll
    for (int dd = 0; dd < 16; dd++) acc[dd] = 0.f;
    #pragma unroll
    for (int j = 0; j < 8; j++) {
        float p = lg[j] * inv;
        const float* vp = &Vs[(r * 8 + j) * 128 + k * 32 + hf * 16];
        #pragma unroll
        for (int dd = 0; dd < 16; dd++) acc[dd] += p * vp[dd];
    }
    #pragma unroll
    for (int t = 0; t < 4; t++)
        *(float4*)&g_oth[base + t * 4] = *(float4*)&acc[t * 4];
}

// ---------------- launch -----------------------------------------------------------
extern "C" void kernel_launch(void* const* d_in, const int* in_sizes, int n_in,
                              void* d_out, int out_size)
{
    const float* states  = (const float*)d_in[0];
    const float* actions = (const float*)d_in[1];
    const float* We      = (const float*)d_in[2];
    const float* be      = (const float*)d_in[3];
    const float* Wse     = (const float*)d_in[4];
    const float* bs      = (const float*)d_in[5];
    const float* Wk      = (const float*)d_in[6];
    const float* Wq      = (const float*)d_in[7];
    const float* Wv      = (const float*)d_in[8];
    const float* bv      = (const float*)d_in[9];
    const float* Wc1     = (const float*)d_in[10];
    const float* bc1     = (const float*)d_in[11];
    const float* Wc2     = (const float*)d_in[12];
    const float* bc2     = (const float*)d_in[13];
    float* out = (float*)d_out;

    float *p_sa, *p_se, *p_K, *p_Q, *p_V;
    cudaGetSymbolAddress((void**)&p_sa,  g_sa);
    cudaGetSymbolAddress((void**)&p_se,  g_se);
    cudaGetSymbolAddress((void**)&p_K,   g_Kb);
    cudaGetSymbolAddress((void**)&p_Q,   g_Qb);
    cudaGetSymbolAddress((void**)&p_V,   g_Vb);

    dim3 grid(BATCH / 128, 1, NAG);
    gemm128_tc<<<grid, 256>>>(states, SDIM, actions, ADIM, We, 0, be, 1, p_sa, SDIM + ADIM);
    gemm128_tc<<<grid, 256>>>(states, SDIM, nullptr, 0,    Wse, 0, bs, 1, p_se, SDIM);
    gemm128_tc<<<grid, 256>>>(p_sa, HID, nullptr, 0, Wk, 1, nullptr, 0, p_K, HID);
    gemm128_tc<<<grid, 256>>>(p_se, HID, nullptr, 0, Wq, 1, nullptr, 0, p_Q, HID);
    gemm128_tc<<<grid, 256>>>(p_sa, HID, nullptr, 0, Wv, 1, bv,      1, p_V, HID);
    attn_kernel<<<BATCH / 4, 256>>>();
    critic_tc<<<grid, 256>>>(actions, Wc1, bc1, Wc2, bc2, out);
}